// round 3
// baseline (speedup 1.0000x reference)
#include <cuda_runtime.h>
#include <cuda_bf16.h>
#include <stdint.h>

// Problem constants (fixed by the dataset)
#define NNODES 8192
#define DIM    256
#define ALPHA  3.0f
#define NEG    0.2f

#define TPB 256                 // threads per block in softmax kernel
#define CPT (NNODES / TPB)      // columns per thread = 32

// Scratch (no cudaMalloc allowed): per-node projected scores
__device__ float g_s1[NNODES];
__device__ float g_s2[NNODES];

// ---------------------------------------------------------------------------
// Kernel 1: s1[i] = tanh(ALPHA * emb1[idx[i],:]) . w[:D]
//           s2[i] = tanh(ALPHA * emb2[idx[i],:]) . w[D:]
// One block (256 threads == DIM) per node; two block reductions fused.
// ---------------------------------------------------------------------------
__global__ void __launch_bounds__(DIM)
score_kernel(const int* __restrict__ idx,
             const float* __restrict__ e1,
             const float* __restrict__ e2,
             const float* __restrict__ w)
{
    const int node = blockIdx.x;
    const int t    = threadIdx.x;
    const int src  = idx[node];

    float v1 = tanhf(ALPHA * e1[(size_t)src * DIM + t]);
    float v2 = tanhf(ALPHA * e2[(size_t)src * DIM + t]);
    float p1 = v1 * w[t];
    float p2 = v2 * w[DIM + t];

    // warp reduce
    #pragma unroll
    for (int o = 16; o > 0; o >>= 1) {
        p1 += __shfl_down_sync(0xffffffffu, p1, o);
        p2 += __shfl_down_sync(0xffffffffu, p2, o);
    }
    __shared__ float sh1[8], sh2[8];
    if ((t & 31) == 0) { sh1[t >> 5] = p1; sh2[t >> 5] = p2; }
    __syncthreads();
    if (t == 0) {
        float a = 0.f, b = 0.f;
        #pragma unroll
        for (int k = 0; k < 8; k++) { a += sh1[k]; b += sh2[k]; }
        g_s1[node] = a;
        g_s2[node] = b;
    }
}

// ---------------------------------------------------------------------------
// Kernel 2: one block per output row i.
//   x[j]   = leaky_relu(s1[i] + s2[j] + b)
//   out[i, idx[j]] = exp(x[j] - max_j x) / sum_j exp(x[j] - max_j x)
// Row cached in registers (CPT=32 floats/thread) -> exactly ONE exp/element.
// s2[] and idx[] (32KB each) stay L1-resident across blocks on an SM.
// ---------------------------------------------------------------------------
__global__ void __launch_bounds__(TPB)
softmax_kernel(const int* __restrict__ idx,
               const float* __restrict__ att_b,
               float* __restrict__ out)
{
    const int i = blockIdx.x;
    const int t = threadIdx.x;

    const float base = g_s1[i] + att_b[0];

    float vals[CPT];
    float m = -1e30f;
    #pragma unroll
    for (int k = 0; k < CPT; k++) {
        const int j = k * TPB + t;
        float x = base + __ldg(&g_s2[j]);
        x = (x > 0.f) ? x : NEG * x;        // leaky_relu
        vals[k] = x;
        m = fmaxf(m, x);
    }

    // block max
    __shared__ float shm[8];
    #pragma unroll
    for (int o = 16; o > 0; o >>= 1)
        m = fmaxf(m, __shfl_xor_sync(0xffffffffu, m, o));
    if ((t & 31) == 0) shm[t >> 5] = m;
    __syncthreads();
    m = shm[0];
    #pragma unroll
    for (int wgi = 1; wgi < 8; wgi++) m = fmaxf(m, shm[wgi]);

    // exp once, accumulate sum
    float sum = 0.f;
    #pragma unroll
    for (int k = 0; k < CPT; k++) {
        float e = __expf(vals[k] - m);
        vals[k] = e;
        sum += e;
    }

    // block sum
    __shared__ float shs[8];
    #pragma unroll
    for (int o = 16; o > 0; o >>= 1)
        sum += __shfl_xor_sync(0xffffffffu, sum, o);
    if ((t & 31) == 0) shs[t >> 5] = sum;
    __syncthreads();
    sum = 0.f;
    #pragma unroll
    for (int wgi = 0; wgi < 8; wgi++) sum += shs[wgi];

    const float inv = 1.0f / sum;

    // scatter store: out[i, idx[j]] = vals * inv
    float* row = out + (size_t)i * NNODES;
    #pragma unroll
    for (int k = 0; k < CPT; k++) {
        const int j = k * TPB + t;
        row[__ldg(&idx[j])] = vals[k] * inv;
    }
}

// ---------------------------------------------------------------------------
// Inputs (metadata order): idx[int32 N], emb1_w[f32 N*D], emb2_w[f32 N*D],
//                          att_w[f32 2D], att_b[f32 1].  Output: f32 N*N.
// ---------------------------------------------------------------------------
extern "C" void kernel_launch(void* const* d_in, const int* in_sizes, int n_in,
                              void* d_out, int out_size)
{
    const int*   idx  = (const int*)  d_in[0];
    const float* e1   = (const float*)d_in[1];
    const float* e2   = (const float*)d_in[2];
    const float* attw = (const float*)d_in[3];
    const float* attb = (const float*)d_in[4];
    float*       out  = (float*)d_out;

    score_kernel<<<NNODES, DIM>>>(idx, e1, e2, attw);
    softmax_kernel<<<NNODES, TPB>>>(idx, attb, out);
}